// round 3
// baseline (speedup 1.0000x reference)
#include <cuda_runtime.h>
#include <math.h>

#define B_     2
#define L_     1024
#define D_     1024
#define INTER_ 2816
#define S_     32
#define NCH    88    // metric-conv channel chunks of 32

// ---------------- scratch (device globals; no allocation allowed) ----------------
__device__ float   g_x2d  [(size_t)B_ * INTER_ * L_];   // x_ffn, channel-major
__device__ float   g_xd   [(size_t)B_ * INTER_ * L_];   // deform output, channel-major
__device__ float   g_ppart[(size_t)B_ * NCH * 7 * L_];  // metric conv partials
__device__ float   g_p    [(size_t)B_ * 7 * L_];        // metric conv result
__device__ ushort4 g_tapi [(size_t)B_ * L_ * 9];        // bilinear corner indices
__device__ float4  g_tapw [(size_t)B_ * L_ * 9];        // bilinear corner weights (validity folded)

// ================= GEMM1: gu = x @ w_gate_up^T, fused SiLU, transposed write ======
// C[f][l] per batch. BM=64 f (gate+up pairs), BN=128 l, BK=16. 256 thr, 4x8 micro x2.
__global__ __launch_bounds__(256, 2) void k_gemm1(const float* __restrict__ x,
                                                  const float* __restrict__ wgu) {
    int b  = blockIdx.z;
    int f0 = blockIdx.y * 64;
    int l0 = blockIdx.x * 128;
    __shared__ float Ag[16][64];
    __shared__ float Au[16][64];
    __shared__ float Bs[16][128];
    int t  = threadIdx.x;
    int tr = t >> 4, tc = t & 15;
    float accg[4][8], accu[4][8];
#pragma unroll
    for (int i = 0; i < 4; i++)
#pragma unroll
        for (int j = 0; j < 8; j++) { accg[i][j] = 0.f; accu[i][j] = 0.f; }

    int lr = t >> 2;          // 0..63
    int kq = (t & 3) << 2;    // 0,4,8,12
    const float* xb  = x + (size_t)b * L_ * D_;
    const float* wg  = wgu + (size_t)(f0 + lr) * D_;
    const float* wu  = wgu + (size_t)(INTER_ + f0 + lr) * D_;
    const float* xr0 = xb + (size_t)(l0 + lr) * D_;
    const float* xr1 = xb + (size_t)(l0 + lr + 64) * D_;

    for (int k0 = 0; k0 < D_; k0 += 16) {
        float4 a4 = *(const float4*)(wg  + k0 + kq);
        float4 u4 = *(const float4*)(wu  + k0 + kq);
        float4 b0 = *(const float4*)(xr0 + k0 + kq);
        float4 b1 = *(const float4*)(xr1 + k0 + kq);
        __syncthreads();
        Ag[kq+0][lr] = a4.x; Ag[kq+1][lr] = a4.y; Ag[kq+2][lr] = a4.z; Ag[kq+3][lr] = a4.w;
        Au[kq+0][lr] = u4.x; Au[kq+1][lr] = u4.y; Au[kq+2][lr] = u4.z; Au[kq+3][lr] = u4.w;
        Bs[kq+0][lr]     = b0.x; Bs[kq+1][lr]     = b0.y; Bs[kq+2][lr]     = b0.z; Bs[kq+3][lr]     = b0.w;
        Bs[kq+0][lr+64]  = b1.x; Bs[kq+1][lr+64]  = b1.y; Bs[kq+2][lr+64]  = b1.z; Bs[kq+3][lr+64]  = b1.w;
        __syncthreads();
#pragma unroll
        for (int k = 0; k < 16; k++) {
            float4 va  = *(float4*)&Ag[k][tr << 2];
            float4 vu  = *(float4*)&Au[k][tr << 2];
            float4 vb0 = *(float4*)&Bs[k][tc << 2];
            float4 vb1 = *(float4*)&Bs[k][64 + (tc << 2)];
            float ar[4] = {va.x, va.y, va.z, va.w};
            float ur[4] = {vu.x, vu.y, vu.z, vu.w};
            float br[8] = {vb0.x, vb0.y, vb0.z, vb0.w, vb1.x, vb1.y, vb1.z, vb1.w};
#pragma unroll
            for (int i = 0; i < 4; i++)
#pragma unroll
                for (int j = 0; j < 8; j++) {
                    accg[i][j] += ar[i] * br[j];
                    accu[i][j] += ur[i] * br[j];
                }
        }
    }
#pragma unroll
    for (int i = 0; i < 4; i++) {
        int f = f0 + (tr << 2) + i;
        float* op = g_x2d + ((size_t)b * INTER_ + f) * L_ + l0;
#pragma unroll
        for (int jg = 0; jg < 2; jg++) {
            float4 v;
            float* vv = (float*)&v;
#pragma unroll
            for (int j = 0; j < 4; j++) {
                float g = accg[i][jg * 4 + j];
                float u = accu[i][jg * 4 + j];
                vv[j] = u * g / (1.f + expf(-g));
            }
            *(float4*)(op + jg * 64 + (tc << 2)) = v;
        }
    }
}

// ================= Metric conv: p_part over channel chunks of 32 ==================
__global__ __launch_bounds__(256) void k_metric(const float* __restrict__ wm) {
    int chunk = blockIdx.x;
    int b     = blockIdx.y;
    __shared__ float img[1024];
    __shared__ float ws[63];
    int t = threadIdx.x;
    float acc[4][7];
#pragma unroll
    for (int j = 0; j < 4; j++)
#pragma unroll
        for (int o = 0; o < 7; o++) acc[j][o] = 0.f;

    for (int ci = 0; ci < 32; ci++) {
        int c = chunk * 32 + ci;
        __syncthreads();
        const float* src = g_x2d + ((size_t)b * INTER_ + c) * L_;
#pragma unroll
        for (int j = 0; j < 4; j++) img[j * 256 + t] = src[j * 256 + t];
        if (t < 63) ws[t] = wm[((size_t)(t / 9) * INTER_ + c) * 9 + (t % 9)];
        __syncthreads();
#pragma unroll
        for (int j = 0; j < 4; j++) {
            int pos = j * 256 + t;
            int y = pos >> 5, xx = pos & 31;
            float nb[9];
#pragma unroll
            for (int ky = 0; ky < 3; ky++)
#pragma unroll
                for (int kx = 0; kx < 3; kx++) {
                    int yy = y + ky - 1, xc = xx + kx - 1;
                    nb[ky * 3 + kx] = (yy >= 0 && yy < 32 && xc >= 0 && xc < 32)
                                          ? img[yy * 32 + xc] : 0.f;
                }
#pragma unroll
            for (int o = 0; o < 7; o++) {
                float s = 0.f;
#pragma unroll
                for (int kk = 0; kk < 9; kk++) s += nb[kk] * ws[o * 9 + kk];
                acc[j][o] += s;
            }
        }
    }
#pragma unroll
    for (int j = 0; j < 4; j++)
#pragma unroll
        for (int o = 0; o < 7; o++)
            g_ppart[((size_t)(b * NCH + chunk) * 7 + o) * L_ + j * 256 + t] = acc[j][o];
}

__global__ void k_metric_reduce(const float* __restrict__ bm) {
    int i = blockIdx.x * 256 + threadIdx.x;
    if (i >= B_ * 7 * L_) return;
    int b   = i / (7 * L_);
    int rem = i % (7 * L_);
    int o   = rem / L_;
    int pos = rem % L_;
    float s = bm[o];
    for (int ch = 0; ch < NCH; ch++)
        s += g_ppart[((size_t)(b * NCH + ch) * 7 + o) * L_ + pos];
    g_p[i] = s;
}

// ================= Tap precompute: bilinear indices + weights (channel-shared) ====
__global__ void k_taps() {
    int i = blockIdx.x * 128 + threadIdx.x;
    if (i >= B_ * L_) return;
    int b = i / L_, pos = i % L_;
    int y = pos >> 5, x = pos & 31;
    const float* pp = g_p + (size_t)b * 7 * L_;
    float m00 = pp[0 * L_ + pos], m01 = pp[1 * L_ + pos];
    float m10 = pp[2 * L_ + pos], m11 = pp[3 * L_ + pos];
    float dry = pp[4 * L_ + pos], drx = pp[5 * L_ + pos];
    float sc  = tanhf(pp[6 * L_ + pos]);
#pragma unroll
    for (int k = 0; k < 9; k++) {
        float py = (float)(k / 3 - 1), px = (float)(k % 3 - 1);
        float oy = sc * (m00 * py + m01 * px) + dry;
        float ox = sc * (m10 * py + m11 * px) + drx;
        float posy = (float)y + py + oy;
        float posx = (float)x + px + ox;
        float y0f = floorf(posy), x0f = floorf(posx);
        float ty = posy - y0f, tx = posx - x0f;
        int y0 = (int)y0f, x0 = (int)x0f;
        int y1 = y0 + 1, x1 = x0 + 1;
        float vy0 = (y0 >= 0 && y0 < S_) ? 1.f : 0.f;
        float vy1 = (y1 >= 0 && y1 < S_) ? 1.f : 0.f;
        float vx0 = (x0 >= 0 && x0 < S_) ? 1.f : 0.f;
        float vx1 = (x1 >= 0 && x1 < S_) ? 1.f : 0.f;
        int cy0 = min(max(y0, 0), S_ - 1), cx0 = min(max(x0, 0), S_ - 1);
        int cy1 = min(max(y1, 0), S_ - 1), cx1 = min(max(x1, 0), S_ - 1);
        ushort4 i4;
        i4.x = (unsigned short)(cy0 * S_ + cx0);
        i4.y = (unsigned short)(cy0 * S_ + cx1);
        i4.z = (unsigned short)(cy1 * S_ + cx0);
        i4.w = (unsigned short)(cy1 * S_ + cx1);
        float4 w4;
        w4.x = (1.f - ty) * (1.f - tx) * vy0 * vx0;
        w4.y = (1.f - ty) * tx        * vy0 * vx1;
        w4.z = ty        * (1.f - tx) * vy1 * vx0;
        w4.w = ty        * tx         * vy1 * vx1;
        g_tapi[(size_t)i * 9 + k] = i4;
        g_tapw[(size_t)i * 9 + k] = w4;
    }
}

// ================= Deformable depthwise conv: 8 channels per block ================
__global__ __launch_bounds__(256) void k_deform(const float* __restrict__ cw_g,
                                                const float* __restrict__ cb_g) {
    int cg = blockIdx.x;
    int b  = blockIdx.y;
    int c0 = cg * 8;
    __shared__ float   img[8 * 1024];   // 32 KB
    __shared__ ushort4 ti[576];         // 4.5 KB
    __shared__ float4  tw[576];         // 9 KB
    __shared__ float   cw[72];
    int t = threadIdx.x;

    const float4* src = (const float4*)(g_x2d + ((size_t)b * INTER_ + c0) * L_);
#pragma unroll
    for (int j = 0; j < 8; j++) ((float4*)img)[j * 256 + t] = src[j * 256 + t];
    if (t < 72) cw[t] = cw_g[c0 * 9 + t];

    int lp = t & 63;
    int cl = t >> 6;        // 0..3
    int cA = cl, cB = cl + 4;
    float bA = cb_g[c0 + cA], bB = cb_g[c0 + cB];
    const float* imA = img + cA * 1024;
    const float* imB = img + cB * 1024;

    for (int chunk = 0; chunk < 16; chunk++) {
        __syncthreads();
        for (int e = t; e < 576; e += 256) {
            size_t gi = ((size_t)b * L_ + chunk * 64) * 9 + e;
            ti[e] = g_tapi[gi];
            tw[e] = g_tapw[gi];
        }
        __syncthreads();
        int pos = chunk * 64 + lp;
        float a0 = bA, a1 = bB;
#pragma unroll
        for (int k = 0; k < 9; k++) {
            int e = lp * 9 + k;
            ushort4 i4 = ti[e];
            float4  w4 = tw[e];
            float s0 = w4.x * imA[i4.x] + w4.y * imA[i4.y] + w4.z * imA[i4.z] + w4.w * imA[i4.w];
            float s1 = w4.x * imB[i4.x] + w4.y * imB[i4.y] + w4.z * imB[i4.z] + w4.w * imB[i4.w];
            a0 += s0 * cw[cA * 9 + k];
            a1 += s1 * cw[cB * 9 + k];
        }
        g_xd[((size_t)b * INTER_ + c0 + cA) * L_ + pos] = a0;
        g_xd[((size_t)b * INTER_ + c0 + cB) * L_ + pos] = a1;
    }
}

// ================= GEMM2: out[l][d] = sum_f xd[f][l] * w_down[d][f] ===============
// BM=128 l, BN=64 d, BK=16; A already transposed in memory (channel-major xd).
__global__ __launch_bounds__(256, 2) void k_gemm2(const float* __restrict__ wd,
                                                  float* __restrict__ out) {
    int b  = blockIdx.z;
    int l0 = blockIdx.y * 128;
    int d0 = blockIdx.x * 64;
    __shared__ float As[16][128];
    __shared__ float Bs[16][64];
    int t  = threadIdx.x;
    int tr = t >> 4, tc = t & 15;
    float acc[8][4];
#pragma unroll
    for (int i = 0; i < 8; i++)
#pragma unroll
        for (int j = 0; j < 4; j++) acc[i][j] = 0.f;

    int kk = t >> 4;          // 0..15
    int ll = (t & 15) * 8;    // 0..120
    int dd = t >> 2;          // 0..63
    int kq = (t & 3) * 4;
    const float* ap = g_xd + ((size_t)b * INTER_ + kk) * L_ + l0 + ll;
    const float* bp = wd + (size_t)(d0 + dd) * INTER_ + kq;

    for (int k0 = 0; k0 < INTER_; k0 += 16) {
        float4 a0 = *(const float4*)(ap + (size_t)k0 * L_);
        float4 a1 = *(const float4*)(ap + (size_t)k0 * L_ + 4);
        float4 w4 = *(const float4*)(bp + k0);
        __syncthreads();
        *(float4*)&As[kk][ll]     = a0;
        *(float4*)&As[kk][ll + 4] = a1;
        Bs[kq + 0][dd] = w4.x; Bs[kq + 1][dd] = w4.y;
        Bs[kq + 2][dd] = w4.z; Bs[kq + 3][dd] = w4.w;
        __syncthreads();
#pragma unroll
        for (int k = 0; k < 16; k++) {
            float4 va0 = *(float4*)&As[k][tr << 2];
            float4 va1 = *(float4*)&As[k][64 + (tr << 2)];
            float4 vb  = *(float4*)&Bs[k][tc << 2];
            float ar[8] = {va0.x, va0.y, va0.z, va0.w, va1.x, va1.y, va1.z, va1.w};
            float br[4] = {vb.x, vb.y, vb.z, vb.w};
#pragma unroll
            for (int i = 0; i < 8; i++)
#pragma unroll
                for (int j = 0; j < 4; j++) acc[i][j] += ar[i] * br[j];
        }
    }
#pragma unroll
    for (int i = 0; i < 8; i++) {
        int l = l0 + ((i < 4) ? ((tr << 2) + i) : (64 + (tr << 2) + (i - 4)));
        float4 v;
        v.x = acc[i][0]; v.y = acc[i][1]; v.z = acc[i][2]; v.w = acc[i][3];
        *(float4*)(out + ((size_t)b * L_ + l) * D_ + d0 + (tc << 2)) = v;
    }
}

// ================================ launch ==========================================
extern "C" void kernel_launch(void* const* d_in, const int* in_sizes, int n_in,
                              void* d_out, int out_size) {
    const float* x   = (const float*)d_in[0];
    const float* wgu = (const float*)d_in[1];
    const float* wm  = (const float*)d_in[2];
    const float* bm  = (const float*)d_in[3];
    const float* cw  = (const float*)d_in[4];
    const float* cb  = (const float*)d_in[5];
    const float* wd  = (const float*)d_in[6];
    float* out = (float*)d_out;

    k_gemm1<<<dim3(8, 44, 2), 256>>>(x, wgu);
    k_metric<<<dim3(NCH, 2), 256>>>(wm);
    k_metric_reduce<<<(B_ * 7 * L_ + 255) / 256, 256>>>(bm);
    k_taps<<<(B_ * L_ + 127) / 128, 128>>>();
    k_deform<<<dim3(INTER_ / 8, 2), 256>>>(cw, cb);
    k_gemm2<<<dim3(D_ / 64, L_ / 128, 2), 256>>>(wd, out);
}

// round 8
// speedup vs baseline: 1.9910x; 1.9910x over previous
#include <cuda_runtime.h>
#include <cstdint>
#include <math.h>

#define B_     2
#define L_     1024
#define D_     1024
#define INTER_ 2816
#define S_     32
#define NCH    88

// ---------------- scratch ----------------
__device__ float   g_x2d [(size_t)B_ * INTER_ * L_];   // x_ffn, channel-major
__device__ float   g_xd  [(size_t)B_ * INTER_ * L_];   // deform out, channel-major
__device__ float   g_xdt [(size_t)B_ * L_ * INTER_];   // deform out, l-major (for GEMM2)
__device__ float   g_ppart[(size_t)B_ * NCH * 7 * L_];
__device__ float   g_p   [(size_t)B_ * 7 * L_];
__device__ ushort4 g_tapi[(size_t)B_ * L_ * 9];
__device__ float4  g_tapw[(size_t)B_ * L_ * 9];

// ---------------- helpers (base-target PTX only: sm_80-class) ----------------
__device__ __forceinline__ uint32_t smem_u32(const void* p) {
    uint32_t a;
    asm("{ .reg .u64 t; cvta.to.shared.u64 t, %1; cvt.u32.u64 %0, t; }" : "=r"(a) : "l"(p));
    return a;
}
__device__ __forceinline__ void ldm_x4(uint32_t* r, uint32_t addr) {
    asm volatile("ldmatrix.sync.aligned.m8n8.x4.shared.b16 {%0,%1,%2,%3}, [%4];"
                 : "=r"(r[0]), "=r"(r[1]), "=r"(r[2]), "=r"(r[3]) : "r"(addr));
}
__device__ __forceinline__ void mma_bf16(float* c, const uint32_t* a, const uint32_t* b) {
    asm volatile("mma.sync.aligned.m16n8k16.row.col.f32.bf16.bf16.f32 "
                 "{%0,%1,%2,%3}, {%4,%5,%6,%7}, {%8,%9}, {%0,%1,%2,%3};"
                 : "+f"(c[0]), "+f"(c[1]), "+f"(c[2]), "+f"(c[3])
                 : "r"(a[0]), "r"(a[1]), "r"(a[2]), "r"(a[3]), "r"(b[0]), "r"(b[1]));
}

// SMEM stage layout (byte offsets within one stage):
//   A_hi [128][40] bf16  @ 0        (pitch 80 B)
//   A_lo                 @ 10240
//   B_hi [128][40] bf16  @ 20480
//   B_lo                 @ 30720
#define PITCH   80
#define OFF_ALO 10240u
#define OFF_BHI 20480u
#define STAGE   40960
#define SMEM_DYN (2 * STAGE)

// convert float4 -> bf16 hi/lo pairs, store as uint2 at hi/lo offsets
__device__ __forceinline__ void cvt_store(char* st, uint32_t off, float4 v) {
    uint32_t h0, h1, l0, l1;
    asm("cvt.rn.bf16x2.f32 %0, %1, %2;" : "=r"(h0) : "f"(v.y), "f"(v.x));
    asm("cvt.rn.bf16x2.f32 %0, %1, %2;" : "=r"(h1) : "f"(v.w), "f"(v.z));
    float r0 = v.x - __uint_as_float(h0 << 16);
    float r1 = v.y - __uint_as_float(h0 & 0xffff0000u);
    float r2 = v.z - __uint_as_float(h1 << 16);
    float r3 = v.w - __uint_as_float(h1 & 0xffff0000u);
    asm("cvt.rn.bf16x2.f32 %0, %1, %2;" : "=r"(l0) : "f"(r1), "f"(r0));
    asm("cvt.rn.bf16x2.f32 %0, %1, %2;" : "=r"(l1) : "f"(r3), "f"(r2));
    *(uint2*)(st + off)           = make_uint2(h0, h1);
    *(uint2*)(st + off + OFF_ALO) = make_uint2(l0, l1);
}

// one K-chunk (32) of HMMA work: 2 k16 steps, 4 Mtiles x 4 Ntiles x 3 split-passes
__device__ __forceinline__ void gemm_compute(uint32_t sb, const int* RB, int wx,
                                             int lane, float acc[4][4][4]) {
    uint32_t laneoff = (uint32_t)((lane & 15) * PITCH + (lane >> 4) * 16);
#pragma unroll
    for (int ks = 0; ks < 2; ks++) {
        uint32_t kb = (uint32_t)ks * 32u;  // 16 bf16 = 32 bytes
        uint32_t ah[4][4], al[4][4];
#pragma unroll
        for (int m = 0; m < 4; m++) {
            uint32_t a = sb + (uint32_t)RB[m] * PITCH + laneoff + kb;
            ldm_x4(ah[m], a);
            ldm_x4(al[m], a + OFF_ALO);
        }
        uint32_t bh[4][2], bl[4][2];
#pragma unroll
        for (int p = 0; p < 2; p++) {
            uint32_t a = sb + OFF_BHI + (uint32_t)(wx * 32 + p * 16) * PITCH + laneoff + kb;
            uint32_t r[4];
            ldm_x4(r, a);
            bh[2*p][0] = r[0]; bh[2*p+1][0] = r[1]; bh[2*p][1] = r[2]; bh[2*p+1][1] = r[3];
            ldm_x4(r, a + OFF_ALO);
            bl[2*p][0] = r[0]; bl[2*p+1][0] = r[1]; bl[2*p][1] = r[2]; bl[2*p+1][1] = r[3];
        }
#pragma unroll
        for (int m = 0; m < 4; m++)
#pragma unroll
            for (int n = 0; n < 4; n++) {
                mma_bf16(acc[m][n], ah[m], bh[n]);
                mma_bf16(acc[m][n], ah[m], bl[n]);
                mma_bf16(acc[m][n], al[m], bh[n]);
            }
    }
}

// ================= GEMM1 (mma.sync bf16 3x): gu = x @ wgu^T, fused SiLU ===========
// A tile rows 0-63 = gate f, 64-127 = up f. N = 128 l columns. K = 1024.
__global__ __launch_bounds__(256, 1) void k_gemm1_mma(const float* __restrict__ x,
                                                      const float* __restrict__ wgu) {
    extern __shared__ char sm[];
    const int t = threadIdx.x, lane = t & 31, wid = t >> 5;
    const int wy = wid >> 2, wx = wid & 3;
    const int b = blockIdx.z, f0 = blockIdx.y * 64, l0 = blockIdx.x * 128;
    const uint32_t sbase = smem_u32(sm);

    const float* gp[8];
    const int c8 = (t & 7) * 4;
#pragma unroll
    for (int p = 0; p < 8; p++) {
        int r = (t >> 3) + (p & 3) * 32;
        if (p < 4) {
            gp[p] = (r < 64) ? wgu + (size_t)(f0 + r) * D_ + c8
                             : wgu + (size_t)(INTER_ + f0 + r - 64) * D_ + c8;
        } else {
            gp[p] = x + ((size_t)b * L_ + l0 + r) * D_ + c8;
        }
    }
    const uint32_t so0 = (uint32_t)((t >> 3) * PITCH + (t & 7) * 8);

    float acc[4][4][4];
#pragma unroll
    for (int m = 0; m < 4; m++)
#pragma unroll
        for (int n = 0; n < 4; n++)
#pragma unroll
            for (int r = 0; r < 4; r++) acc[m][n][r] = 0.f;

    int RB[4] = { wy * 32, wy * 32 + 16, 64 + wy * 32, 64 + wy * 32 + 16 };

    {   // chunk 0
#pragma unroll
        for (int p = 0; p < 8; p++) {
            float4 v = *(const float4*)(gp[p]);
            uint32_t off = (uint32_t)((p & 3) * 32 * PITCH) + so0 + ((p < 4) ? 0u : OFF_BHI);
            cvt_store(sm, off, v);
        }
    }
    __syncthreads();

    const int NC = D_ / 32;  // 32
    for (int c = 0; c < NC; c++) {
        int s = c & 1;
        float4 pr[8];
        if (c + 1 < NC) {
#pragma unroll
            for (int p = 0; p < 8; p++) pr[p] = *(const float4*)(gp[p] + (c + 1) * 32);
        }
        gemm_compute(sbase + (uint32_t)s * STAGE, RB, wx, lane, acc);
        if (c + 1 < NC) {
            char* st = sm + (s ^ 1) * STAGE;
#pragma unroll
            for (int p = 0; p < 8; p++) {
                uint32_t off = (uint32_t)((p & 3) * 32 * PITCH) + so0 + ((p < 4) ? 0u : OFF_BHI);
                cvt_store(st, off, pr[p]);
            }
        }
        __syncthreads();
    }

    // epilogue: gate = acc[mi], up = acc[mi+2]; SiLU fuse; channel-major write
    const int g = lane >> 2, tg2 = (lane & 3) * 2;
#pragma unroll
    for (int mi = 0; mi < 2; mi++)
#pragma unroll
        for (int ni = 0; ni < 4; ni++)
#pragma unroll
            for (int h = 0; h < 2; h++) {
                float gv0 = acc[mi][ni][h * 2],     gv1 = acc[mi][ni][h * 2 + 1];
                float uv0 = acc[mi + 2][ni][h * 2], uv1 = acc[mi + 2][ni][h * 2 + 1];
                float o0 = uv0 * gv0 / (1.f + expf(-gv0));
                float o1 = uv1 * gv1 / (1.f + expf(-gv1));
                int f = f0 + wy * 32 + mi * 16 + g + h * 8;
                int lc = l0 + wx * 32 + ni * 8 + tg2;
                *(float2*)(g_x2d + ((size_t)b * INTER_ + f) * L_ + lc) = make_float2(o0, o1);
            }
}

// ================= GEMM2 (mma.sync bf16 3x): out[l][d] = xdt[l][:] @ wd[d][:] =====
__global__ __launch_bounds__(256, 1) void k_gemm2_mma(const float* __restrict__ wd,
                                                      float* __restrict__ out) {
    extern __shared__ char sm[];
    const int t = threadIdx.x, lane = t & 31, wid = t >> 5;
    const int wy = wid >> 2, wx = wid & 3;
    const int b = blockIdx.z, l0 = blockIdx.y * 128, d0 = blockIdx.x * 128;
    const uint32_t sbase = smem_u32(sm);

    const float* gp[8];
    const int c8 = (t & 7) * 4;
#pragma unroll
    for (int p = 0; p < 8; p++) {
        int r = (t >> 3) + (p & 3) * 32;
        if (p < 4) gp[p] = g_xdt + ((size_t)b * L_ + l0 + r) * INTER_ + c8;
        else       gp[p] = wd + (size_t)(d0 + r) * INTER_ + c8;
    }
    const uint32_t so0 = (uint32_t)((t >> 3) * PITCH + (t & 7) * 8);

    float acc[4][4][4];
#pragma unroll
    for (int m = 0; m < 4; m++)
#pragma unroll
        for (int n = 0; n < 4; n++)
#pragma unroll
            for (int r = 0; r < 4; r++) acc[m][n][r] = 0.f;

    int RB[4] = { wy * 64, wy * 64 + 16, wy * 64 + 32, wy * 64 + 48 };

    {
#pragma unroll
        for (int p = 0; p < 8; p++) {
            float4 v = *(const float4*)(gp[p]);
            uint32_t off = (uint32_t)((p & 3) * 32 * PITCH) + so0 + ((p < 4) ? 0u : OFF_BHI);
            cvt_store(sm, off, v);
        }
    }
    __syncthreads();

    const int NC = INTER_ / 32;  // 88
    for (int c = 0; c < NC; c++) {
        int s = c & 1;
        float4 pr[8];
        if (c + 1 < NC) {
#pragma unroll
            for (int p = 0; p < 8; p++) pr[p] = *(const float4*)(gp[p] + (c + 1) * 32);
        }
        gemm_compute(sbase + (uint32_t)s * STAGE, RB, wx, lane, acc);
        if (c + 1 < NC) {
            char* st = sm + (s ^ 1) * STAGE;
#pragma unroll
            for (int p = 0; p < 8; p++) {
                uint32_t off = (uint32_t)((p & 3) * 32 * PITCH) + so0 + ((p < 4) ? 0u : OFF_BHI);
                cvt_store(st, off, pr[p]);
            }
        }
        __syncthreads();
    }

    const int g = lane >> 2, tg2 = (lane & 3) * 2;
#pragma unroll
    for (int mi = 0; mi < 4; mi++)
#pragma unroll
        for (int ni = 0; ni < 4; ni++)
#pragma unroll
            for (int h = 0; h < 2; h++) {
                int l = l0 + wy * 64 + mi * 16 + g + h * 8;
                int d = d0 + wx * 32 + ni * 8 + tg2;
                *(float2*)(out + ((size_t)b * L_ + l) * D_ + d) =
                    make_float2(acc[mi][ni][h * 2], acc[mi][ni][h * 2 + 1]);
            }
}

// ================= Metric conv =====================================================
__global__ __launch_bounds__(256) void k_metric(const float* __restrict__ wm) {
    int chunk = blockIdx.x;
    int b = blockIdx.y;
    __shared__ float img[1024];
    __shared__ float ws[63];
    int t = threadIdx.x;
    float acc[4][7];
#pragma unroll
    for (int j = 0; j < 4; j++)
#pragma unroll
        for (int o = 0; o < 7; o++) acc[j][o] = 0.f;

    for (int ci = 0; ci < 32; ci++) {
        int c = chunk * 32 + ci;
        __syncthreads();
        const float* src = g_x2d + ((size_t)b * INTER_ + c) * L_;
#pragma unroll
        for (int j = 0; j < 4; j++) img[j * 256 + t] = src[j * 256 + t];
        if (t < 63) ws[t] = wm[((size_t)(t / 9) * INTER_ + c) * 9 + (t % 9)];
        __syncthreads();
#pragma unroll
        for (int j = 0; j < 4; j++) {
            int pos = j * 256 + t;
            int y = pos >> 5, xx = pos & 31;
            float nb[9];
#pragma unroll
            for (int ky = 0; ky < 3; ky++)
#pragma unroll
                for (int kx = 0; kx < 3; kx++) {
                    int yy = y + ky - 1, xc = xx + kx - 1;
                    nb[ky * 3 + kx] = (yy >= 0 && yy < 32 && xc >= 0 && xc < 32)
                                          ? img[yy * 32 + xc] : 0.f;
                }
#pragma unroll
            for (int o = 0; o < 7; o++) {
                float s = 0.f;
#pragma unroll
                for (int kk = 0; kk < 9; kk++) s += nb[kk] * ws[o * 9 + kk];
                acc[j][o] += s;
            }
        }
    }
#pragma unroll
    for (int j = 0; j < 4; j++)
#pragma unroll
        for (int o = 0; o < 7; o++)
            g_ppart[((size_t)(b * NCH + chunk) * 7 + o) * L_ + j * 256 + t] = acc[j][o];
}

__global__ void k_metric_reduce(const float* __restrict__ bm) {
    int i = blockIdx.x * 256 + threadIdx.x;
    if (i >= B_ * 7 * L_) return;
    int b = i / (7 * L_);
    int rem = i % (7 * L_);
    int o = rem / L_;
    int pos = rem % L_;
    float s = bm[o];
    for (int ch = 0; ch < NCH; ch++)
        s += g_ppart[((size_t)(b * NCH + ch) * 7 + o) * L_ + pos];
    g_p[i] = s;
}

// ================= Tap precompute ==================================================
__global__ void k_taps() {
    int i = blockIdx.x * 128 + threadIdx.x;
    if (i >= B_ * L_) return;
    int b = i / L_, pos = i % L_;
    int y = pos >> 5, x = pos & 31;
    const float* pp = g_p + (size_t)b * 7 * L_;
    float m00 = pp[0 * L_ + pos], m01 = pp[1 * L_ + pos];
    float m10 = pp[2 * L_ + pos], m11 = pp[3 * L_ + pos];
    float dry = pp[4 * L_ + pos], drx = pp[5 * L_ + pos];
    float sc = tanhf(pp[6 * L_ + pos]);
#pragma unroll
    for (int k = 0; k < 9; k++) {
        float py = (float)(k / 3 - 1), px = (float)(k % 3 - 1);
        float oy = sc * (m00 * py + m01 * px) + dry;
        float ox = sc * (m10 * py + m11 * px) + drx;
        float posy = (float)y + py + oy;
        float posx = (float)x + px + ox;
        float y0f = floorf(posy), x0f = floorf(posx);
        float ty = posy - y0f, tx = posx - x0f;
        int y0 = (int)y0f, x0 = (int)x0f;
        int y1 = y0 + 1, x1 = x0 + 1;
        float vy0 = (y0 >= 0 && y0 < S_) ? 1.f : 0.f;
        float vy1 = (y1 >= 0 && y1 < S_) ? 1.f : 0.f;
        float vx0 = (x0 >= 0 && x0 < S_) ? 1.f : 0.f;
        float vx1 = (x1 >= 0 && x1 < S_) ? 1.f : 0.f;
        int cy0 = min(max(y0, 0), S_ - 1), cx0 = min(max(x0, 0), S_ - 1);
        int cy1 = min(max(y1, 0), S_ - 1), cx1 = min(max(x1, 0), S_ - 1);
        ushort4 i4;
        i4.x = (unsigned short)(cy0 * S_ + cx0);
        i4.y = (unsigned short)(cy0 * S_ + cx1);
        i4.z = (unsigned short)(cy1 * S_ + cx0);
        i4.w = (unsigned short)(cy1 * S_ + cx1);
        float4 w4;
        w4.x = (1.f - ty) * (1.f - tx) * vy0 * vx0;
        w4.y = (1.f - ty) * tx * vy0 * vx1;
        w4.z = ty * (1.f - tx) * vy1 * vx0;
        w4.w = ty * tx * vy1 * vx1;
        g_tapi[(size_t)i * 9 + k] = i4;
        g_tapw[(size_t)i * 9 + k] = w4;
    }
}

// ================= Deformable depthwise conv ======================================
__global__ __launch_bounds__(256) void k_deform(const float* __restrict__ cw_g,
                                                const float* __restrict__ cb_g) {
    int cg = blockIdx.x;
    int b = blockIdx.y;
    int c0 = cg * 8;
    __shared__ float img[8 * 1024];
    __shared__ ushort4 ti[576];
    __shared__ float4 tw[576];
    __shared__ float cw[72];
    int t = threadIdx.x;

    const float4* src = (const float4*)(g_x2d + ((size_t)b * INTER_ + c0) * L_);
#pragma unroll
    for (int j = 0; j < 8; j++) ((float4*)img)[j * 256 + t] = src[j * 256 + t];
    if (t < 72) cw[t] = cw_g[c0 * 9 + t];

    int lp = t & 63;
    int cl = t >> 6;
    int cA = cl, cB = cl + 4;
    float bA = cb_g[c0 + cA], bB = cb_g[c0 + cB];
    const float* imA = img + cA * 1024;
    const float* imB = img + cB * 1024;

    for (int chunk = 0; chunk < 16; chunk++) {
        __syncthreads();
        for (int e = t; e < 576; e += 256) {
            size_t gi = ((size_t)b * L_ + chunk * 64) * 9 + e;
            ti[e] = g_tapi[gi];
            tw[e] = g_tapw[gi];
        }
        __syncthreads();
        int pos = chunk * 64 + lp;
        float a0 = bA, a1 = bB;
#pragma unroll
        for (int k = 0; k < 9; k++) {
            int e = lp * 9 + k;
            ushort4 i4 = ti[e];
            float4 w4 = tw[e];
            float s0 = w4.x * imA[i4.x] + w4.y * imA[i4.y] + w4.z * imA[i4.z] + w4.w * imA[i4.w];
            float s1 = w4.x * imB[i4.x] + w4.y * imB[i4.y] + w4.z * imB[i4.z] + w4.w * imB[i4.w];
            a0 += s0 * cw[cA * 9 + k];
            a1 += s1 * cw[cB * 9 + k];
        }
        g_xd[((size_t)b * INTER_ + c0 + cA) * L_ + pos] = a0;
        g_xd[((size_t)b * INTER_ + c0 + cB) * L_ + pos] = a1;
    }
}

// ================= Transpose xd[c][l] -> xdt[l][c] ================================
__global__ void k_transpose() {
    __shared__ float tile[32][33];
    int b = blockIdx.z;
    int c0 = blockIdx.x * 32;
    int p0 = blockIdx.y * 32;
    int tx = threadIdx.x, ty = threadIdx.y;
#pragma unroll
    for (int j = 0; j < 32; j += 8)
        tile[ty + j][tx] = g_xd[((size_t)b * INTER_ + c0 + ty + j) * L_ + p0 + tx];
    __syncthreads();
#pragma unroll
    for (int j = 0; j < 32; j += 8)
        g_xdt[((size_t)b * L_ + p0 + ty + j) * INTER_ + c0 + tx] = tile[tx][ty + j];
}

// ================================ launch ==========================================
extern "C" void kernel_launch(void* const* d_in, const int* in_sizes, int n_in,
                              void* d_out, int out_size) {
    const float* x   = (const float*)d_in[0];
    const float* wgu = (const float*)d_in[1];
    const float* wm  = (const float*)d_in[2];
    const float* bm  = (const float*)d_in[3];
    const float* cw  = (const float*)d_in[4];
    const float* cb  = (const float*)d_in[5];
    const float* wd  = (const float*)d_in[6];
    float* out = (float*)d_out;

    cudaFuncSetAttribute(k_gemm1_mma, cudaFuncAttributeMaxDynamicSharedMemorySize, SMEM_DYN);
    cudaFuncSetAttribute(k_gemm2_mma, cudaFuncAttributeMaxDynamicSharedMemorySize, SMEM_DYN);

    k_gemm1_mma<<<dim3(8, 44, 2), 256, SMEM_DYN>>>(x, wgu);
    k_metric<<<dim3(NCH, 2), 256>>>(wm);
    k_metric_reduce<<<(B_ * 7 * L_ + 255) / 256, 256>>>(bm);
    k_taps<<<(B_ * L_ + 127) / 128, 128>>>();
    k_deform<<<dim3(INTER_ / 8, 2), 256>>>(cw, cb);
    k_transpose<<<dim3(INTER_ / 32, L_ / 32, 2), dim3(32, 8)>>>();
    k_gemm2_mma<<<dim3(D_ / 128, L_ / 128, 2), 256, SMEM_DYN>>>(wd, out);
}